// round 15
// baseline (speedup 1.0000x reference)
#include <cuda_runtime.h>

typedef unsigned long long ull;
typedef unsigned int u32;
typedef unsigned short u16;

#define NB   64
#define CC   64
#define TT   300
#define VV   25
#define TV   7500
#define ICn  16
#define OCn  64
#define KS   3
#define KT   9
#define YSZ  30720000
#define BN_CNT 480000.0f
#define TCN_TILES 59              // ceil(7500/128)

// ---------------- f32x2 helpers (FFMA2) ----------------
__device__ __forceinline__ ull fma2(ull a, ull b, ull c) {
    ull d;
    asm("fma.rn.f32x2 %0,%1,%2,%3;" : "=l"(d) : "l"(a), "l"(b), "l"(c));
    return d;
}
__device__ __forceinline__ ull dup2(float v) {
    ull d; asm("mov.b64 %0,{%1,%1};" : "=l"(d) : "f"(v)); return d;
}
__device__ __forceinline__ float2 unpk(ull a) {
    float2 r; asm("mov.b64 {%0,%1},%2;" : "=f"(r.x), "=f"(r.y) : "l"(a)); return r;
}
__device__ __forceinline__ float wredsum(float v) {
    #pragma unroll
    for (int s = 16; s; s >>= 1) v += __shfl_xor_sync(0xffffffffu, v, s);
    return v;
}
// ---------------- bf16 helpers ----------------
__device__ __forceinline__ u16 f2bf(float f) {
    u16 h; asm("cvt.rn.bf16.f32 %0,%1;" : "=h"(h) : "f"(f)); return h;
}
__device__ __forceinline__ u32 bfpack(float lo, float hi) {
    u32 d; asm("cvt.rn.satfinite.bf16x2.f32 %0,%2,%1;" : "=r"(d) : "f"(lo), "f"(hi)); return d;
}
__device__ __forceinline__ u32 hfma2b(u32 a, u32 b, u32 c) {
    u32 d; asm("fma.rn.bf16x2 %0,%1,%2,%3;" : "=r"(d) : "r"(a), "r"(b), "r"(c)); return d;
}
__device__ __forceinline__ u32 splat16(u16 h) {
    u32 d; asm("mov.b32 %0,{%1,%1};" : "=r"(d) : "h"(h)); return d;
}
__device__ __forceinline__ float lo2f(u32 r) { return __uint_as_float(r << 16); }
__device__ __forceinline__ float hi2f(u32 r) { return __uint_as_float(r & 0xffff0000u); }

// ---------------- scratch ----------------
__device__ __align__(16) u16 g_fa[KS*NB*ICn*TV];   // bf16
__device__ __align__(16) u16 g_fb[KS*NB*ICn*TV];   // bf16
__device__ float g_Spart[KS*NB*16*625];
__device__ float g_S [KS*NB*VV*VV];
__device__ __align__(16) u16 g_wdtb[KS*CC*OCn];    // Wd transposed [kc][o], bf16
__device__ float g_y1[(size_t)NB*OCn*TV];
__device__ float g_ps1[64*9600];
__device__ float g_pq1[64*9600];
__device__ float g_ps2[64*(TCN_TILES*64)];
__device__ float g_pq2[64*(TCN_TILES*64)];
__device__ float g_stats[4*OCn];

// ---------------- K1: fa/fb 1x1 projections (bf16 store) + Wd prep ---------
__global__ void __launch_bounds__(256) k_projab(const float* __restrict__ x,
        const float* __restrict__ Wa, const float* __restrict__ ba,
        const float* __restrict__ Wb, const float* __restrict__ bb,
        const float* __restrict__ Wd) {
    __shared__ __align__(16) float ws2[64*96];
    int tid = threadIdx.x;
    if (blockIdx.x == 0 && blockIdx.y == 0) {
        for (int i = tid; i < KS*CC*OCn; i += 256) {
            int kc = i >> 6, o = i & 63;
            int k = kc >> 6, c = kc & 63;
            g_wdtb[i] = f2bf(Wd[(k*64 + o)*64 + c]);
        }
    }
    for (int i = tid; i < 48*64; i += 256) {
        int r = i >> 6, c = i & 63;
        ws2[c*96 + r]      = Wa[i];
        ws2[c*96 + 48 + r] = Wb[i];
    }
    __syncthreads();
    int n = blockIdx.y;
    int base = blockIdx.x * 1024 + tid;
    const float* xn = x + n * CC * TV;

    for (int p = 0; p < 6; p++) {
        ull acc2[8][4];
        #pragma unroll
        for (int jj = 0; jj < 8; jj++)
            #pragma unroll
            for (int m = 0; m < 4; m++) acc2[jj][m] = 0ull;
        #pragma unroll 2
        for (int c = 0; c < 64; c++) {
            ull xd[4];
            #pragma unroll
            for (int m = 0; m < 4; m++) {
                int tv = base + m * 256;
                xd[m] = dup2((tv < TV) ? xn[c * TV + tv] : 0.f);
            }
            const ull* wp = (const ull*)(ws2 + c*96 + p*16);
            #pragma unroll
            for (int jj = 0; jj < 8; jj++) {
                ull w2 = wp[jj];
                #pragma unroll
                for (int m = 0; m < 4; m++) acc2[jj][m] = fma2(w2, xd[m], acc2[jj][m]);
            }
        }
        #pragma unroll
        for (int jj = 0; jj < 8; jj++) {
            #pragma unroll
            for (int h = 0; h < 2; h++) {
                int r = p*16 + 2*jj + h;
                float bias; u16* out;
                if (r < 48) {
                    bias = ba[r];
                    out = g_fa + (size_t)((r >> 4) * NB * ICn + n * ICn + (r & 15)) * TV;
                } else {
                    int r2 = r - 48;
                    bias = bb[r2];
                    out = g_fb + (size_t)((r2 >> 4) * NB * ICn + n * ICn + (r2 & 15)) * TV;
                }
                #pragma unroll
                for (int m = 0; m < 4; m++) {
                    int tv = base + m * 256;
                    if (tv < TV) {
                        float2 f = unpk(acc2[jj][m]);
                        out[tv] = f2bf((h ? f.y : f.x) + bias);
                    }
                }
            }
        }
    }
}

// ---------------- K2a: partial attention dots (bf16 in, fp32 smem) ---------
__global__ void __launch_bounds__(640) k_scoreP() {
    int kn = blockIdx.y, ch = blockIdx.x;
    const u32* fa32 = (const u32*)(g_fa + (size_t)kn * ICn * TV) + ch * 3750;
    const u32* fb32 = (const u32*)(g_fb + (size_t)kn * ICn * TV) + ch * 3750;
    __shared__ float as[60*25], bs[60*25];
    int tid = threadIdx.x;
    int v = tid / 25, w = tid - v * 25;
    bool act = tid < 625;
    float acc = 0.f;
    for (int it = 0; it < 5; it++) {
        for (int i = tid; i < 750; i += 640) {
            u32 wa = fa32[it * 750 + i];
            u32 wb = fb32[it * 750 + i];
            as[2*i] = lo2f(wa); as[2*i+1] = hi2f(wa);
            bs[2*i] = lo2f(wb); bs[2*i+1] = hi2f(wb);
        }
        __syncthreads();
        if (act) {
            #pragma unroll 10
            for (int d = 0; d < 60; d++) acc = fmaf(as[d*25 + v], bs[d*25 + w], acc);
        }
        __syncthreads();
    }
    if (act) g_Spart[(kn * 16 + ch) * 625 + tid] = acc;
}

// ---------------- K2b: reduce partials + softmax + A ----------------
__global__ void __launch_bounds__(640) k_softS(const float* __restrict__ adj,
                                               const float* __restrict__ PA) {
    int kn = blockIdx.x;
    int kk = kn / NB, n = kn % NB;
    __shared__ float Ssm[625];
    int tid = threadIdx.x;
    if (tid < 625) {
        float s = 0.f;
        const float* p = g_Spart + (size_t)kn * 16 * 625 + tid;
        #pragma unroll
        for (int ch = 0; ch < 16; ch++) s += p[ch * 625];
        Ssm[tid] = s * (1.f / 4800.f);
    }
    __syncthreads();
    if (tid < 25) {
        int wq = tid;
        float m = -1e30f;
        #pragma unroll
        for (int vi = 0; vi < 25; vi++) m = fmaxf(m, Ssm[vi*25 + wq]);
        float e[25]; float s = 0.f;
        #pragma unroll
        for (int vi = 0; vi < 25; vi++) { e[vi] = expf(Ssm[vi*25 + wq] - m); s += e[vi]; }
        float inv = 1.f / s;
        #pragma unroll
        for (int vi = 0; vi < 25; vi++) {
            int ai = (kk * VV + vi) * VV + wq;
            g_S[kn * 625 + vi * 25 + wq] = e[vi] * inv + adj[ai] + PA[ai];
        }
    }
}

// ---------------- K3: fused GCN v7 (R12, measured 596us) ----------------
#define G7_S   0
#define G7_X   2100
#define G7_ZB  5364
#define G7_TOT 10548
__global__ void __launch_bounds__(256, 4) k_gcn(const float* __restrict__ x,
        const float* __restrict__ bd) {
    extern __shared__ __align__(16) float sm[];
    float* S_s = sm + G7_S;
    float* x_s = sm + G7_X;
    u32*   Zb  = (u32*)(sm + G7_ZB);
    int tid = threadIdx.x;
    int n = blockIdx.y;
    int tile0 = blockIdx.x * 50;

    for (int i = tid; i < 1875; i += 256) {
        int k = i / 625, r = i - k * 625;
        int v = r / 25, w = r - v * 25;
        S_s[k*700 + v*28 + w] = g_S[(k * NB + n) * 625 + r];
    }
    for (int i = tid; i < 225; i += 256) {
        int k = i / 75, rr = i - k * 75;
        int v = rr / 3, pw = rr - v * 3;
        S_s[k*700 + v*28 + 25 + pw] = 0.f;
    }
    for (int i = tid; i < 3200; i += 256) {
        int c = i / 50, j = i - c * 50;
        x_s[c*51 + j] = x[(n * CC + c) * TV + tile0 + j];
    }
    __syncthreads();

    if (tid < 192) {
        int kc = tid, k = kc >> 6, c = kc & 63;
        ull acc[26];
        #pragma unroll
        for (int p = 0; p < 26; p++) acc[p] = 0ull;
        const float* xrow = x_s + c * 51;
        const float* Srow = S_s + k * 700;
        #pragma unroll 5
        for (int v = 0; v < 25; v++) {
            ull xd0 = dup2(xrow[v]);
            ull xd1 = dup2(xrow[25 + v]);
            const ulonglong2* sp2 = (const ulonglong2*)(Srow + v * 28);
            ull sv[13];
            #pragma unroll
            for (int q = 0; q < 6; q++) {
                ulonglong2 u = sp2[q];
                sv[2*q] = u.x; sv[2*q+1] = u.y;
            }
            sv[12] = ((const ull*)(Srow + v * 28))[6];
            #pragma unroll
            for (int p = 0; p < 13; p++) {
                acc[p]      = fma2(sv[p], xd0, acc[p]);
                acc[13 + p] = fma2(sv[p], xd1, acc[13 + p]);
            }
        }
        u32* zr = Zb + kc * 27;
        #pragma unroll
        for (int p = 0; p < 13; p++) {
            float2 f0 = unpk(acc[p]);
            float2 f1 = unpk(acc[13 + p]);
            zr[p]      = bfpack(f0.x, f0.y);
            zr[13 + p] = bfpack(f1.x, f1.y);
        }
    }
    __syncthreads();

    int ty = tid >> 5, tx = tid & 31;
    int ob = ty * 8;
    u32 accb[4][2];
    #pragma unroll
    for (int a = 0; a < 4; a++) { accb[a][0] = 0u; accb[a][1] = 0u; }
    const uint4* __restrict__ wg = (const uint4*)g_wdtb + (ob >> 3);
    #pragma unroll 4
    for (int kc = 0; kc < 192; kc++) {
        uint4 wq = __ldg(wg + kc * 8);
        const u16* zrow = (const u16*)(Zb + kc * 27);
        u32 z0 = splat16(zrow[tx]);
        u32 z1 = splat16(zrow[33 + tx]);
        accb[0][0] = hfma2b(wq.x, z0, accb[0][0]);
        accb[0][1] = hfma2b(wq.x, z1, accb[0][1]);
        accb[1][0] = hfma2b(wq.y, z0, accb[1][0]);
        accb[1][1] = hfma2b(wq.y, z1, accb[1][1]);
        accb[2][0] = hfma2b(wq.z, z0, accb[2][0]);
        accb[2][1] = hfma2b(wq.z, z1, accb[2][1]);
        accb[3][0] = hfma2b(wq.w, z0, accb[3][0]);
        accb[3][1] = hfma2b(wq.w, z1, accb[3][1]);
    }
    int blk = n * 150 + blockIdx.x;
    bool v1 = (tx < 18);
    #pragma unroll
    for (int a = 0; a < 4; a++) {
        int o0 = ob + 2*a;
        float b0 = bd[o0]   + bd[64+o0]   + bd[128+o0];
        float b1 = bd[o0+1] + bd[64+o0+1] + bd[128+o0+1];
        float vx0 = lo2f(accb[a][0]) + b0, vy0 = hi2f(accb[a][0]) + b1;
        float vx1 = lo2f(accb[a][1]) + b0, vy1 = hi2f(accb[a][1]) + b1;
        size_t base0 = (size_t)(n*OCn + o0) * TV + tile0;
        g_y1[base0 + tx] = vx0;
        g_y1[base0 + TV + tx] = vy0;
        if (v1) {
            g_y1[base0 + 32 + tx] = vx1;
            g_y1[base0 + TV + 32 + tx] = vy1;
        }
        float sx = vx0 + (v1 ? vx1 : 0.f);
        float qx = vx0*vx0 + (v1 ? vx1*vx1 : 0.f);
        float sy = vy0 + (v1 ? vy1 : 0.f);
        float qy = vy0*vy0 + (v1 ? vy1*vy1 : 0.f);
        sx = wredsum(sx); qx = wredsum(qx);
        sy = wredsum(sy); qy = wredsum(qy);
        if (tx == 0) {
            g_ps1[o0*9600 + blk] = sx;  g_pq1[o0*9600 + blk] = qx;
            g_ps1[(o0+1)*9600 + blk] = sy;  g_pq1[(o0+1)*9600 + blk] = qy;
        }
    }
}

// ---------------- BN final reductions (deterministic) ----------------
__device__ __forceinline__ void bnsum_body(const float* ps, const float* pq,
                                           int cnt, int off) {
    int o = blockIdx.x;
    __shared__ float sh[512];
    float s = 0.f, q = 0.f;
    for (int i = threadIdx.x; i < cnt; i += 256) {
        s += ps[o*cnt + i];
        q += pq[o*cnt + i];
    }
    sh[threadIdx.x] = s; sh[256 + threadIdx.x] = q;
    __syncthreads();
    for (int st = 128; st; st >>= 1) {
        if (threadIdx.x < st) {
            sh[threadIdx.x] += sh[threadIdx.x + st];
            sh[256 + threadIdx.x] += sh[256 + threadIdx.x + st];
        }
        __syncthreads();
    }
    if (threadIdx.x == 0) {
        g_stats[off + o] = sh[0];
        g_stats[off + 64 + o] = sh[256];
    }
}
__global__ void k_bnsum1() { bnsum_body(g_ps1, g_pq1, 9600, 0); }
__global__ void k_bnsum2() { bnsum_body(g_ps2, g_pq2, TCN_TILES*64, 128); }

// ---------------- K6: temporal conv v2 — 128-tw tiles, 4 CTAs/SM ------------
__global__ void __launch_bounds__(256, 4) k_tcn(const float* __restrict__ Wt,
                                                const float* __restrict__ bt,
                                                const float* __restrict__ x,
                                                const float* __restrict__ g1,
                                                const float* __restrict__ b1,
                                                float* __restrict__ out) {
    __shared__ float ys[8 * 328];
    __shared__ __align__(16) float wsm[8 * 9 * 64];
    __shared__ float csc[64], csh[64];
    int n = blockIdx.y;
    int tile0 = blockIdx.x * 128;
    int tid = threadIdx.x;
    int ty = tid >> 5, tx = tid & 31;
    int ob = ty * 8;
    if (tid < 64) {
        const float inv = 1.f / BN_CNT;
        float mu  = g_stats[tid] * inv;
        float var = fmaf(-mu, mu, g_stats[64 + tid] * inv);
        float sc  = rsqrtf(var + 1e-5f) * g1[tid];
        csc[tid] = sc;
        csh[tid] = fmaf(-mu, sc, b1[tid]);
    }
    ull acc2[4][4];
    #pragma unroll
    for (int a = 0; a < 4; a++)
        #pragma unroll
        for (int j = 0; j < 4; j++) acc2[a][j] = 0ull;
    __syncthreads();

    for (int c0 = 0; c0 < 64; c0 += 8) {
        __syncthreads();
        for (int i = tid; i < 8 * 328; i += 256) {
            int c = i / 328, off = i - c * 328;
            int tw = tile0 - 100 + off;
            int cc = c0 + c;
            float v = 0.f;
            if (tw >= 0 && tw < TV) {
                size_t gi = (size_t)(n * CC + cc) * TV + tw;
                float raw = g_y1[gi];
                v = fmaf(raw, csc[cc], csh[cc]) + x[gi];
                v = fmaxf(v, 0.f);
            }
            ys[i] = v;
        }
        for (int i = tid; i < 8 * 9 * 64; i += 256) {
            int o = i & 63, ck = i >> 6;
            int c = ck / 9, kt = ck - c * 9;
            wsm[i] = Wt[(o * 64 + c0 + c) * 9 + kt];
        }
        __syncthreads();
        for (int c = 0; c < 8; c++) {
            #pragma unroll 3
            for (int kt = 0; kt < 9; kt++) {
                int ybase = c * 328 + 100 + 25 * (kt - 4) + tx;
                ull yd[4];
                #pragma unroll
                for (int j = 0; j < 4; j++) yd[j] = dup2(ys[ybase + 32 * j]);
                const ulonglong2* wp2 = (const ulonglong2*)(wsm + (c * 9 + kt) * 64 + ob);
                ulonglong2 wA = wp2[0];
                ulonglong2 wB = wp2[1];
                #pragma unroll
                for (int j = 0; j < 4; j++) {
                    acc2[0][j] = fma2(wA.x, yd[j], acc2[0][j]);
                    acc2[1][j] = fma2(wA.y, yd[j], acc2[1][j]);
                    acc2[2][j] = fma2(wB.x, yd[j], acc2[2][j]);
                    acc2[3][j] = fma2(wB.y, yd[j], acc2[3][j]);
                }
            }
        }
    }
    int blk = n * TCN_TILES + blockIdx.x;
    #pragma unroll
    for (int a = 0; a < 4; a++) {
        int o0 = ob + 2*a;
        float b0 = bt[o0], b1v = bt[o0+1];
        float sx = 0.f, qx = 0.f, sy = 0.f, qy = 0.f;
        #pragma unroll
        for (int j = 0; j < 4; j++) {
            int tw = tile0 + tx + 32 * j;
            if (tw < TV) {
                float2 f = unpk(acc2[a][j]);
                float vx = f.x + b0, vy = f.y + b1v;
                out[(size_t)(n * OCn + o0  ) * TV + tw] = vx;
                out[(size_t)(n * OCn + o0+1) * TV + tw] = vy;
                sx += vx; qx += vx*vx;
                sy += vy; qy += vy*vy;
            }
        }
        sx = wredsum(sx); qx = wredsum(qx);
        sy = wredsum(sy); qy = wredsum(qy);
        if (tx == 0) {
            g_ps2[o0*(TCN_TILES*64) + blk] = sx;  g_pq2[o0*(TCN_TILES*64) + blk] = qx;
            g_ps2[(o0+1)*(TCN_TILES*64) + blk] = sy;  g_pq2[(o0+1)*(TCN_TILES*64) + blk] = qy;
        }
    }
}

// ---------------- BN2 apply + residual + relu ----------------
__global__ void k_bn2(float* __restrict__ out, const float* __restrict__ x,
                      const float* __restrict__ g2, const float* __restrict__ b2) {
    int idx = blockIdx.x * 256 + threadIdx.x;
    if (idx >= YSZ) return;
    int c = (idx / TV) & 63;
    const float inv = 1.f / BN_CNT;
    float mu  = g_stats[128 + c] * inv;
    float var = fmaf(-mu, mu, g_stats[192 + c] * inv);
    float sc  = rsqrtf(var + 1e-5f) * g2[c];
    float v   = (out[idx] - mu) * sc + b2[c] + x[idx];
    out[idx] = fmaxf(v, 0.f);
}

// ---------------- adj passthrough ----------------
__global__ void k_copyadj(const float* __restrict__ adj, float* __restrict__ out, int count) {
    int i = blockIdx.x * 256 + threadIdx.x;
    if (i < count) out[YSZ + i] = adj[i];
}

// ---------------- launch ----------------
extern "C" void kernel_launch(void* const* d_in, const int* in_sizes, int n_in,
                              void* d_out, int out_size) {
    const float* x   = (const float*)d_in[0];
    const float* adj = (const float*)d_in[1];
    const float* PA  = (const float*)d_in[2];
    const float* Wa  = (const float*)d_in[3];
    const float* ba  = (const float*)d_in[4];
    const float* Wb  = (const float*)d_in[5];
    const float* bb  = (const float*)d_in[6];
    const float* Wd  = (const float*)d_in[7];
    const float* bd  = (const float*)d_in[8];
    const float* g1  = (const float*)d_in[9];
    const float* b1  = (const float*)d_in[10];
    const float* Wt  = (const float*)d_in[11];
    const float* bt  = (const float*)d_in[12];
    const float* g2  = (const float*)d_in[13];
    const float* b2  = (const float*)d_in[14];
    float* out = (float*)d_out;

    static int smem_set = 0;
    if (!smem_set) {
        cudaFuncSetAttribute(k_gcn, cudaFuncAttributeMaxDynamicSharedMemorySize,
                             G7_TOT * sizeof(float));
        smem_set = 1;
    }

    k_projab<<<dim3(8, 64), 256>>>(x, Wa, ba, Wb, bb, Wd);      // 1 (+Wd prep)
    k_scoreP<<<dim3(16, 192), 640>>>();                          // 2
    int adjcount = out_size - YSZ;
    if (adjcount > 0) {
        if (adjcount > 3 * VV * VV) adjcount = 3 * VV * VV;
        k_copyadj<<<8, 256>>>(adj, out, adjcount);               // 3
    }
    k_softS<<<192, 640>>>(adj, PA);                              // 4 -> profiled
    k_gcn<<<dim3(150, 64), 256, G7_TOT * sizeof(float)>>>(x, bd); // 5

    k_bnsum1<<<64, 256>>>();                                     // 6

    k_tcn<<<dim3(TCN_TILES, 64), 256>>>(Wt, bt, x, g1, b1, out); // 7

    k_bnsum2<<<64, 256>>>();
    k_bn2<<<(YSZ + 255) / 256, 256>>>(out, x, g2, b2);
}

// round 16
// speedup vs baseline: 1.0243x; 1.0243x over previous
#include <cuda_runtime.h>

typedef unsigned long long ull;
typedef unsigned int u32;
typedef unsigned short u16;

#define NB   64
#define CC   64
#define TT   300
#define VV   25
#define TV   7500
#define ICn  16
#define OCn  64
#define KS   3
#define KT   9
#define YSZ  30720000
#define BN_CNT 480000.0f
#define TCN_TW    160
#define TCN_TILES 47              // ceil(7500/160)
#define TCN_HALO  360             // 160 + 2*100

// ---------------- f32x2 helpers (FFMA2) ----------------
__device__ __forceinline__ ull fma2(ull a, ull b, ull c) {
    ull d;
    asm("fma.rn.f32x2 %0,%1,%2,%3;" : "=l"(d) : "l"(a), "l"(b), "l"(c));
    return d;
}
__device__ __forceinline__ ull dup2(float v) {
    ull d; asm("mov.b64 %0,{%1,%1};" : "=l"(d) : "f"(v)); return d;
}
__device__ __forceinline__ float2 unpk(ull a) {
    float2 r; asm("mov.b64 {%0,%1},%2;" : "=f"(r.x), "=f"(r.y) : "l"(a)); return r;
}
__device__ __forceinline__ float wredsum(float v) {
    #pragma unroll
    for (int s = 16; s; s >>= 1) v += __shfl_xor_sync(0xffffffffu, v, s);
    return v;
}
// ---------------- bf16 helpers ----------------
__device__ __forceinline__ u16 f2bf(float f) {
    u16 h; asm("cvt.rn.bf16.f32 %0,%1;" : "=h"(h) : "f"(f)); return h;
}
__device__ __forceinline__ u32 bfpack(float lo, float hi) {
    u32 d; asm("cvt.rn.satfinite.bf16x2.f32 %0,%2,%1;" : "=r"(d) : "f"(lo), "f"(hi)); return d;
}
__device__ __forceinline__ u32 hfma2b(u32 a, u32 b, u32 c) {
    u32 d; asm("fma.rn.bf16x2 %0,%1,%2,%3;" : "=r"(d) : "r"(a), "r"(b), "r"(c)); return d;
}
__device__ __forceinline__ u32 splat16(u16 h) {
    u32 d; asm("mov.b32 %0,{%1,%1};" : "=r"(d) : "h"(h)); return d;
}
__device__ __forceinline__ float lo2f(u32 r) { return __uint_as_float(r << 16); }
__device__ __forceinline__ float hi2f(u32 r) { return __uint_as_float(r & 0xffff0000u); }

// ---------------- scratch ----------------
__device__ __align__(16) u16 g_fa[KS*NB*ICn*TV];   // bf16
__device__ __align__(16) u16 g_fb[KS*NB*ICn*TV];   // bf16
__device__ float g_Spart[KS*NB*16*625];
__device__ float g_S [KS*NB*VV*VV];
__device__ __align__(16) u16 g_wdtb[KS*CC*OCn];    // Wd transposed [kc][o], bf16
__device__ float g_y1[(size_t)NB*OCn*TV];
__device__ float g_ps1[64*9600];
__device__ float g_pq1[64*9600];
__device__ float g_ps2[64*(TCN_TILES*64)];
__device__ float g_pq2[64*(TCN_TILES*64)];
__device__ float g_stats[4*OCn];

// ---------------- K1: fa/fb 1x1 projections (bf16 store) + Wd prep ---------
__global__ void __launch_bounds__(256) k_projab(const float* __restrict__ x,
        const float* __restrict__ Wa, const float* __restrict__ ba,
        const float* __restrict__ Wb, const float* __restrict__ bb,
        const float* __restrict__ Wd) {
    __shared__ __align__(16) float ws2[64*96];
    int tid = threadIdx.x;
    if (blockIdx.x == 0 && blockIdx.y == 0) {
        for (int i = tid; i < KS*CC*OCn; i += 256) {
            int kc = i >> 6, o = i & 63;
            int k = kc >> 6, c = kc & 63;
            g_wdtb[i] = f2bf(Wd[(k*64 + o)*64 + c]);
        }
    }
    for (int i = tid; i < 48*64; i += 256) {
        int r = i >> 6, c = i & 63;
        ws2[c*96 + r]      = Wa[i];
        ws2[c*96 + 48 + r] = Wb[i];
    }
    __syncthreads();
    int n = blockIdx.y;
    int base = blockIdx.x * 1024 + tid;
    const float* xn = x + n * CC * TV;

    for (int p = 0; p < 6; p++) {
        ull acc2[8][4];
        #pragma unroll
        for (int jj = 0; jj < 8; jj++)
            #pragma unroll
            for (int m = 0; m < 4; m++) acc2[jj][m] = 0ull;
        #pragma unroll 2
        for (int c = 0; c < 64; c++) {
            ull xd[4];
            #pragma unroll
            for (int m = 0; m < 4; m++) {
                int tv = base + m * 256;
                xd[m] = dup2((tv < TV) ? xn[c * TV + tv] : 0.f);
            }
            const ull* wp = (const ull*)(ws2 + c*96 + p*16);
            #pragma unroll
            for (int jj = 0; jj < 8; jj++) {
                ull w2 = wp[jj];
                #pragma unroll
                for (int m = 0; m < 4; m++) acc2[jj][m] = fma2(w2, xd[m], acc2[jj][m]);
            }
        }
        #pragma unroll
        for (int jj = 0; jj < 8; jj++) {
            #pragma unroll
            for (int h = 0; h < 2; h++) {
                int r = p*16 + 2*jj + h;
                float bias; u16* out;
                if (r < 48) {
                    bias = ba[r];
                    out = g_fa + (size_t)((r >> 4) * NB * ICn + n * ICn + (r & 15)) * TV;
                } else {
                    int r2 = r - 48;
                    bias = bb[r2];
                    out = g_fb + (size_t)((r2 >> 4) * NB * ICn + n * ICn + (r2 & 15)) * TV;
                }
                #pragma unroll
                for (int m = 0; m < 4; m++) {
                    int tv = base + m * 256;
                    if (tv < TV) {
                        float2 f = unpk(acc2[jj][m]);
                        out[tv] = f2bf((h ? f.y : f.x) + bias);
                    }
                }
            }
        }
    }
}

// ---------------- K2a: partial attention dots (bf16 in, fp32 smem) ---------
__global__ void __launch_bounds__(640) k_scoreP() {
    int kn = blockIdx.y, ch = blockIdx.x;
    const u32* fa32 = (const u32*)(g_fa + (size_t)kn * ICn * TV) + ch * 3750;
    const u32* fb32 = (const u32*)(g_fb + (size_t)kn * ICn * TV) + ch * 3750;
    __shared__ float as[60*25], bs[60*25];
    int tid = threadIdx.x;
    int v = tid / 25, w = tid - v * 25;
    bool act = tid < 625;
    float acc = 0.f;
    for (int it = 0; it < 5; it++) {
        for (int i = tid; i < 750; i += 640) {
            u32 wa = fa32[it * 750 + i];
            u32 wb = fb32[it * 750 + i];
            as[2*i] = lo2f(wa); as[2*i+1] = hi2f(wa);
            bs[2*i] = lo2f(wb); bs[2*i+1] = hi2f(wb);
        }
        __syncthreads();
        if (act) {
            #pragma unroll 10
            for (int d = 0; d < 60; d++) acc = fmaf(as[d*25 + v], bs[d*25 + w], acc);
        }
        __syncthreads();
    }
    if (act) g_Spart[(kn * 16 + ch) * 625 + tid] = acc;
}

// ---------------- K2b: reduce partials + softmax + A ----------------
__global__ void __launch_bounds__(640) k_softS(const float* __restrict__ adj,
                                               const float* __restrict__ PA) {
    int kn = blockIdx.x;
    int kk = kn / NB, n = kn % NB;
    __shared__ float Ssm[625];
    int tid = threadIdx.x;
    if (tid < 625) {
        float s = 0.f;
        const float* p = g_Spart + (size_t)kn * 16 * 625 + tid;
        #pragma unroll
        for (int ch = 0; ch < 16; ch++) s += p[ch * 625];
        Ssm[tid] = s * (1.f / 4800.f);
    }
    __syncthreads();
    if (tid < 25) {
        int wq = tid;
        float m = -1e30f;
        #pragma unroll
        for (int vi = 0; vi < 25; vi++) m = fmaxf(m, Ssm[vi*25 + wq]);
        float e[25]; float s = 0.f;
        #pragma unroll
        for (int vi = 0; vi < 25; vi++) { e[vi] = expf(Ssm[vi*25 + wq] - m); s += e[vi]; }
        float inv = 1.f / s;
        #pragma unroll
        for (int vi = 0; vi < 25; vi++) {
            int ai = (kk * VV + vi) * VV + wq;
            g_S[kn * 625 + vi * 25 + wq] = e[vi] * inv + adj[ai] + PA[ai];
        }
    }
}

// ---------------- K3: fused GCN v7 (R12, measured 596us) ----------------
#define G7_S   0
#define G7_X   2100
#define G7_ZB  5364
#define G7_TOT 10548
__global__ void __launch_bounds__(256, 4) k_gcn(const float* __restrict__ x,
        const float* __restrict__ bd) {
    extern __shared__ __align__(16) float sm[];
    float* S_s = sm + G7_S;
    float* x_s = sm + G7_X;
    u32*   Zb  = (u32*)(sm + G7_ZB);
    int tid = threadIdx.x;
    int n = blockIdx.y;
    int tile0 = blockIdx.x * 50;

    for (int i = tid; i < 1875; i += 256) {
        int k = i / 625, r = i - k * 625;
        int v = r / 25, w = r - v * 25;
        S_s[k*700 + v*28 + w] = g_S[(k * NB + n) * 625 + r];
    }
    for (int i = tid; i < 225; i += 256) {
        int k = i / 75, rr = i - k * 75;
        int v = rr / 3, pw = rr - v * 3;
        S_s[k*700 + v*28 + 25 + pw] = 0.f;
    }
    for (int i = tid; i < 3200; i += 256) {
        int c = i / 50, j = i - c * 50;
        x_s[c*51 + j] = x[(n * CC + c) * TV + tile0 + j];
    }
    __syncthreads();

    if (tid < 192) {
        int kc = tid, k = kc >> 6, c = kc & 63;
        ull acc[26];
        #pragma unroll
        for (int p = 0; p < 26; p++) acc[p] = 0ull;
        const float* xrow = x_s + c * 51;
        const float* Srow = S_s + k * 700;
        #pragma unroll 5
        for (int v = 0; v < 25; v++) {
            ull xd0 = dup2(xrow[v]);
            ull xd1 = dup2(xrow[25 + v]);
            const ulonglong2* sp2 = (const ulonglong2*)(Srow + v * 28);
            ull sv[13];
            #pragma unroll
            for (int q = 0; q < 6; q++) {
                ulonglong2 u = sp2[q];
                sv[2*q] = u.x; sv[2*q+1] = u.y;
            }
            sv[12] = ((const ull*)(Srow + v * 28))[6];
            #pragma unroll
            for (int p = 0; p < 13; p++) {
                acc[p]      = fma2(sv[p], xd0, acc[p]);
                acc[13 + p] = fma2(sv[p], xd1, acc[13 + p]);
            }
        }
        u32* zr = Zb + kc * 27;
        #pragma unroll
        for (int p = 0; p < 13; p++) {
            float2 f0 = unpk(acc[p]);
            float2 f1 = unpk(acc[13 + p]);
            zr[p]      = bfpack(f0.x, f0.y);
            zr[13 + p] = bfpack(f1.x, f1.y);
        }
    }
    __syncthreads();

    int ty = tid >> 5, tx = tid & 31;
    int ob = ty * 8;
    u32 accb[4][2];
    #pragma unroll
    for (int a = 0; a < 4; a++) { accb[a][0] = 0u; accb[a][1] = 0u; }
    const uint4* __restrict__ wg = (const uint4*)g_wdtb + (ob >> 3);
    #pragma unroll 4
    for (int kc = 0; kc < 192; kc++) {
        uint4 wq = __ldg(wg + kc * 8);
        const u16* zrow = (const u16*)(Zb + kc * 27);
        u32 z0 = splat16(zrow[tx]);
        u32 z1 = splat16(zrow[33 + tx]);
        accb[0][0] = hfma2b(wq.x, z0, accb[0][0]);
        accb[0][1] = hfma2b(wq.x, z1, accb[0][1]);
        accb[1][0] = hfma2b(wq.y, z0, accb[1][0]);
        accb[1][1] = hfma2b(wq.y, z1, accb[1][1]);
        accb[2][0] = hfma2b(wq.z, z0, accb[2][0]);
        accb[2][1] = hfma2b(wq.z, z1, accb[2][1]);
        accb[3][0] = hfma2b(wq.w, z0, accb[3][0]);
        accb[3][1] = hfma2b(wq.w, z1, accb[3][1]);
    }
    int blk = n * 150 + blockIdx.x;
    bool v1 = (tx < 18);
    #pragma unroll
    for (int a = 0; a < 4; a++) {
        int o0 = ob + 2*a;
        float b0 = bd[o0]   + bd[64+o0]   + bd[128+o0];
        float b1 = bd[o0+1] + bd[64+o0+1] + bd[128+o0+1];
        float vx0 = lo2f(accb[a][0]) + b0, vy0 = hi2f(accb[a][0]) + b1;
        float vx1 = lo2f(accb[a][1]) + b0, vy1 = hi2f(accb[a][1]) + b1;
        size_t base0 = (size_t)(n*OCn + o0) * TV + tile0;
        g_y1[base0 + tx] = vx0;
        g_y1[base0 + TV + tx] = vy0;
        if (v1) {
            g_y1[base0 + 32 + tx] = vx1;
            g_y1[base0 + TV + 32 + tx] = vy1;
        }
        float sx = vx0 + (v1 ? vx1 : 0.f);
        float qx = vx0*vx0 + (v1 ? vx1*vx1 : 0.f);
        float sy = vy0 + (v1 ? vy1 : 0.f);
        float qy = vy0*vy0 + (v1 ? vy1*vy1 : 0.f);
        sx = wredsum(sx); qx = wredsum(qx);
        sy = wredsum(sy); qy = wredsum(qy);
        if (tx == 0) {
            g_ps1[o0*9600 + blk] = sx;  g_pq1[o0*9600 + blk] = qx;
            g_ps1[(o0+1)*9600 + blk] = sy;  g_pq1[(o0+1)*9600 + blk] = qy;
        }
    }
}

// ---------------- BN final reductions (deterministic) ----------------
__device__ __forceinline__ void bnsum_body(const float* ps, const float* pq,
                                           int cnt, int off) {
    int o = blockIdx.x;
    __shared__ float sh[512];
    float s = 0.f, q = 0.f;
    for (int i = threadIdx.x; i < cnt; i += 256) {
        s += ps[o*cnt + i];
        q += pq[o*cnt + i];
    }
    sh[threadIdx.x] = s; sh[256 + threadIdx.x] = q;
    __syncthreads();
    for (int st = 128; st; st >>= 1) {
        if (threadIdx.x < st) {
            sh[threadIdx.x] += sh[threadIdx.x + st];
            sh[256 + threadIdx.x] += sh[256 + threadIdx.x + st];
        }
        __syncthreads();
    }
    if (threadIdx.x == 0) {
        g_stats[off + o] = sh[0];
        g_stats[off + 64 + o] = sh[256];
    }
}
__global__ void k_bnsum1() { bnsum_body(g_ps1, g_pq1, 9600, 0); }
__global__ void k_bnsum2() { bnsum_body(g_ps2, g_pq2, TCN_TILES*64, 128); }

// ---------------- K6: temporal conv v3 — 160-tw tiles, 3 CTAs/SM, no spills -
__global__ void __launch_bounds__(256, 3) k_tcn(const float* __restrict__ Wt,
                                                const float* __restrict__ bt,
                                                const float* __restrict__ x,
                                                const float* __restrict__ g1,
                                                const float* __restrict__ b1,
                                                float* __restrict__ out) {
    __shared__ float ys[8 * TCN_HALO];
    __shared__ __align__(16) float wsm[8 * 9 * 64];
    __shared__ float csc[64], csh[64];
    int n = blockIdx.y;
    int tile0 = blockIdx.x * TCN_TW;
    int tid = threadIdx.x;
    int ty = tid >> 5, tx = tid & 31;
    int ob = ty * 8;
    if (tid < 64) {
        const float inv = 1.f / BN_CNT;
        float mu  = g_stats[tid] * inv;
        float var = fmaf(-mu, mu, g_stats[64 + tid] * inv);
        float sc  = rsqrtf(var + 1e-5f) * g1[tid];
        csc[tid] = sc;
        csh[tid] = fmaf(-mu, sc, b1[tid]);
    }
    ull acc2[4][5];
    #pragma unroll
    for (int a = 0; a < 4; a++)
        #pragma unroll
        for (int j = 0; j < 5; j++) acc2[a][j] = 0ull;
    __syncthreads();

    for (int c0 = 0; c0 < 64; c0 += 8) {
        __syncthreads();
        for (int i = tid; i < 8 * TCN_HALO; i += 256) {
            int c = i / TCN_HALO, off = i - c * TCN_HALO;
            int tw = tile0 - 100 + off;
            int cc = c0 + c;
            float v = 0.f;
            if (tw >= 0 && tw < TV) {
                size_t gi = (size_t)(n * CC + cc) * TV + tw;
                float raw = g_y1[gi];
                v = fmaf(raw, csc[cc], csh[cc]) + x[gi];
                v = fmaxf(v, 0.f);
            }
            ys[i] = v;
        }
        for (int i = tid; i < 8 * 9 * 64; i += 256) {
            int o = i & 63, ck = i >> 6;
            int c = ck / 9, kt = ck - c * 9;
            wsm[i] = Wt[(o * 64 + c0 + c) * 9 + kt];
        }
        __syncthreads();
        for (int c = 0; c < 8; c++) {
            #pragma unroll 3
            for (int kt = 0; kt < 9; kt++) {
                int ybase = c * TCN_HALO + 100 + 25 * (kt - 4) + tx;
                ull yd[5];
                #pragma unroll
                for (int j = 0; j < 5; j++) yd[j] = dup2(ys[ybase + 32 * j]);
                const ulonglong2* wp2 = (const ulonglong2*)(wsm + (c * 9 + kt) * 64 + ob);
                ulonglong2 wA = wp2[0];
                ulonglong2 wB = wp2[1];
                #pragma unroll
                for (int j = 0; j < 5; j++) {
                    acc2[0][j] = fma2(wA.x, yd[j], acc2[0][j]);
                    acc2[1][j] = fma2(wA.y, yd[j], acc2[1][j]);
                    acc2[2][j] = fma2(wB.x, yd[j], acc2[2][j]);
                    acc2[3][j] = fma2(wB.y, yd[j], acc2[3][j]);
                }
            }
        }
    }
    int blk = n * TCN_TILES + blockIdx.x;
    #pragma unroll
    for (int a = 0; a < 4; a++) {
        int o0 = ob + 2*a;
        float b0 = bt[o0], b1v = bt[o0+1];
        float sx = 0.f, qx = 0.f, sy = 0.f, qy = 0.f;
        #pragma unroll
        for (int j = 0; j < 5; j++) {
            int tw = tile0 + tx + 32 * j;
            if (tw < TV) {
                float2 f = unpk(acc2[a][j]);
                float vx = f.x + b0, vy = f.y + b1v;
                out[(size_t)(n * OCn + o0  ) * TV + tw] = vx;
                out[(size_t)(n * OCn + o0+1) * TV + tw] = vy;
                sx += vx; qx += vx*vx;
                sy += vy; qy += vy*vy;
            }
        }
        sx = wredsum(sx); qx = wredsum(qx);
        sy = wredsum(sy); qy = wredsum(qy);
        if (tx == 0) {
            g_ps2[o0*(TCN_TILES*64) + blk] = sx;  g_pq2[o0*(TCN_TILES*64) + blk] = qx;
            g_ps2[(o0+1)*(TCN_TILES*64) + blk] = sy;  g_pq2[(o0+1)*(TCN_TILES*64) + blk] = qy;
        }
    }
}

// ---------------- BN2 apply + residual + relu ----------------
__global__ void k_bn2(float* __restrict__ out, const float* __restrict__ x,
                      const float* __restrict__ g2, const float* __restrict__ b2) {
    int idx = blockIdx.x * 256 + threadIdx.x;
    if (idx >= YSZ) return;
    int c = (idx / TV) & 63;
    const float inv = 1.f / BN_CNT;
    float mu  = g_stats[128 + c] * inv;
    float var = fmaf(-mu, mu, g_stats[192 + c] * inv);
    float sc  = rsqrtf(var + 1e-5f) * g2[c];
    float v   = (out[idx] - mu) * sc + b2[c] + x[idx];
    out[idx] = fmaxf(v, 0.f);
}

// ---------------- adj passthrough ----------------
__global__ void k_copyadj(const float* __restrict__ adj, float* __restrict__ out, int count) {
    int i = blockIdx.x * 256 + threadIdx.x;
    if (i < count) out[YSZ + i] = adj[i];
}

// ---------------- launch ----------------
extern "C" void kernel_launch(void* const* d_in, const int* in_sizes, int n_in,
                              void* d_out, int out_size) {
    const float* x   = (const float*)d_in[0];
    const float* adj = (const float*)d_in[1];
    const float* PA  = (const float*)d_in[2];
    const float* Wa  = (const float*)d_in[3];
    const float* ba  = (const float*)d_in[4];
    const float* Wb  = (const float*)d_in[5];
    const float* bb  = (const float*)d_in[6];
    const float* Wd  = (const float*)d_in[7];
    const float* bd  = (const float*)d_in[8];
    const float* g1  = (const float*)d_in[9];
    const float* b1  = (const float*)d_in[10];
    const float* Wt  = (const float*)d_in[11];
    const float* bt  = (const float*)d_in[12];
    const float* g2  = (const float*)d_in[13];
    const float* b2  = (const float*)d_in[14];
    float* out = (float*)d_out;

    static int smem_set = 0;
    if (!smem_set) {
        cudaFuncSetAttribute(k_gcn, cudaFuncAttributeMaxDynamicSharedMemorySize,
                             G7_TOT * sizeof(float));
        smem_set = 1;
    }

    k_projab<<<dim3(8, 64), 256>>>(x, Wa, ba, Wb, bb, Wd);      // 1 (+Wd prep)
    k_scoreP<<<dim3(16, 192), 640>>>();                          // 2
    k_softS<<<192, 640>>>(adj, PA);                              // 3
    k_gcn<<<dim3(150, 64), 256, G7_TOT * sizeof(float)>>>(x, bd); // 4 -> profiled

    int adjcount = out_size - YSZ;
    if (adjcount > 0) {
        if (adjcount > 3 * VV * VV) adjcount = 3 * VV * VV;
        k_copyadj<<<8, 256>>>(adj, out, adjcount);               // 5
    }
    k_bnsum1<<<64, 256>>>();                                     // 6

    k_tcn<<<dim3(TCN_TILES, 64), 256>>>(Wt, bt, x, g1, b1, out); // 7

    k_bnsum2<<<64, 256>>>();
    k_bn2<<<(YSZ + 255) / 256, 256>>>(out, x, g2, b2);
}

// round 17
// speedup vs baseline: 1.1365x; 1.1096x over previous
#include <cuda_runtime.h>
#include <cuda_fp16.h>

typedef unsigned long long ull;
typedef unsigned int u32;
typedef unsigned short u16;

#define NB   64
#define CC   64
#define TT   300
#define VV   25
#define TV   7500
#define ICn  16
#define OCn  64
#define KS   3
#define KT   9
#define YSZ  30720000
#define BN_CNT 480000.0f

// ---------------- f32x2 helpers (FFMA2) ----------------
__device__ __forceinline__ ull fma2(ull a, ull b, ull c) {
    ull d;
    asm("fma.rn.f32x2 %0,%1,%2,%3;" : "=l"(d) : "l"(a), "l"(b), "l"(c));
    return d;
}
__device__ __forceinline__ ull dup2(float v) {
    ull d; asm("mov.b64 %0,{%1,%1};" : "=l"(d) : "f"(v)); return d;
}
__device__ __forceinline__ float2 unpk(ull a) {
    float2 r; asm("mov.b64 {%0,%1},%2;" : "=f"(r.x), "=f"(r.y) : "l"(a)); return r;
}
__device__ __forceinline__ float wredsum(float v) {
    #pragma unroll
    for (int s = 16; s; s >>= 1) v += __shfl_xor_sync(0xffffffffu, v, s);
    return v;
}
// ---------------- bf16 helpers ----------------
__device__ __forceinline__ u16 f2bf(float f) {
    u16 h; asm("cvt.rn.bf16.f32 %0,%1;" : "=h"(h) : "f"(f)); return h;
}
__device__ __forceinline__ u32 bfpack(float lo, float hi) {
    u32 d; asm("cvt.rn.satfinite.bf16x2.f32 %0,%2,%1;" : "=r"(d) : "f"(lo), "f"(hi)); return d;
}
__device__ __forceinline__ u32 hfma2b(u32 a, u32 b, u32 c) {
    u32 d; asm("fma.rn.bf16x2 %0,%1,%2,%3;" : "=r"(d) : "r"(a), "r"(b), "r"(c)); return d;
}
__device__ __forceinline__ u32 splat16(u16 h) {
    u32 d; asm("mov.b32 %0,{%1,%1};" : "=r"(d) : "h"(h)); return d;
}
__device__ __forceinline__ float lo2f(u32 r) { return __uint_as_float(r << 16); }
__device__ __forceinline__ float hi2f(u32 r) { return __uint_as_float(r & 0xffff0000u); }

// ---------------- scratch ----------------
__device__ __align__(16) u16 g_fa[KS*NB*ICn*TV];   // bf16
__device__ __align__(16) u16 g_fb[KS*NB*ICn*TV];   // bf16
__device__ float g_Spart[KS*NB*16*625];
__device__ float g_S [KS*NB*VV*VV];
__device__ __align__(16) u16 g_wdtb[KS*CC*OCn];    // Wd transposed [kc][o], bf16
__device__ float g_y1[(size_t)NB*OCn*TV];
__device__ __align__(16) u16 g_z[YSZ];             // fp16 z = relu(bn1(y1)+x)
__device__ float g_ps1[64*9600];
__device__ float g_pq1[64*9600];
__device__ float g_ps2[64*1920];
__device__ float g_pq2[64*1920];
__device__ float g_stats[4*OCn];

// ---------------- K1: fa/fb 1x1 projections (bf16 store) + Wd prep ---------
__global__ void __launch_bounds__(256) k_projab(const float* __restrict__ x,
        const float* __restrict__ Wa, const float* __restrict__ ba,
        const float* __restrict__ Wb, const float* __restrict__ bb,
        const float* __restrict__ Wd) {
    __shared__ __align__(16) float ws2[64*96];
    int tid = threadIdx.x;
    if (blockIdx.x == 0 && blockIdx.y == 0) {
        for (int i = tid; i < KS*CC*OCn; i += 256) {
            int kc = i >> 6, o = i & 63;
            int k = kc >> 6, c = kc & 63;
            g_wdtb[i] = f2bf(Wd[(k*64 + o)*64 + c]);
        }
    }
    for (int i = tid; i < 48*64; i += 256) {
        int r = i >> 6, c = i & 63;
        ws2[c*96 + r]      = Wa[i];
        ws2[c*96 + 48 + r] = Wb[i];
    }
    __syncthreads();
    int n = blockIdx.y;
    int base = blockIdx.x * 1024 + tid;
    const float* xn = x + n * CC * TV;

    for (int p = 0; p < 6; p++) {
        ull acc2[8][4];
        #pragma unroll
        for (int jj = 0; jj < 8; jj++)
            #pragma unroll
            for (int m = 0; m < 4; m++) acc2[jj][m] = 0ull;
        #pragma unroll 2
        for (int c = 0; c < 64; c++) {
            ull xd[4];
            #pragma unroll
            for (int m = 0; m < 4; m++) {
                int tv = base + m * 256;
                xd[m] = dup2((tv < TV) ? xn[c * TV + tv] : 0.f);
            }
            const ull* wp = (const ull*)(ws2 + c*96 + p*16);
            #pragma unroll
            for (int jj = 0; jj < 8; jj++) {
                ull w2 = wp[jj];
                #pragma unroll
                for (int m = 0; m < 4; m++) acc2[jj][m] = fma2(w2, xd[m], acc2[jj][m]);
            }
        }
        #pragma unroll
        for (int jj = 0; jj < 8; jj++) {
            #pragma unroll
            for (int h = 0; h < 2; h++) {
                int r = p*16 + 2*jj + h;
                float bias; u16* out;
                if (r < 48) {
                    bias = ba[r];
                    out = g_fa + (size_t)((r >> 4) * NB * ICn + n * ICn + (r & 15)) * TV;
                } else {
                    int r2 = r - 48;
                    bias = bb[r2];
                    out = g_fb + (size_t)((r2 >> 4) * NB * ICn + n * ICn + (r2 & 15)) * TV;
                }
                #pragma unroll
                for (int m = 0; m < 4; m++) {
                    int tv = base + m * 256;
                    if (tv < TV) {
                        float2 f = unpk(acc2[jj][m]);
                        out[tv] = f2bf((h ? f.y : f.x) + bias);
                    }
                }
            }
        }
    }
}

// ---------------- K2a: partial attention dots (bf16 in, fp32 smem) ---------
__global__ void __launch_bounds__(640) k_scoreP() {
    int kn = blockIdx.y, ch = blockIdx.x;
    const u32* fa32 = (const u32*)(g_fa + (size_t)kn * ICn * TV) + ch * 3750;
    const u32* fb32 = (const u32*)(g_fb + (size_t)kn * ICn * TV) + ch * 3750;
    __shared__ float as[60*25], bs[60*25];
    int tid = threadIdx.x;
    int v = tid / 25, w = tid - v * 25;
    bool act = tid < 625;
    float acc = 0.f;
    for (int it = 0; it < 5; it++) {
        for (int i = tid; i < 750; i += 640) {
            u32 wa = fa32[it * 750 + i];
            u32 wb = fb32[it * 750 + i];
            as[2*i] = lo2f(wa); as[2*i+1] = hi2f(wa);
            bs[2*i] = lo2f(wb); bs[2*i+1] = hi2f(wb);
        }
        __syncthreads();
        if (act) {
            #pragma unroll 10
            for (int d = 0; d < 60; d++) acc = fmaf(as[d*25 + v], bs[d*25 + w], acc);
        }
        __syncthreads();
    }
    if (act) g_Spart[(kn * 16 + ch) * 625 + tid] = acc;
}

// ---------------- K2b: reduce partials + softmax + A ----------------
__global__ void __launch_bounds__(640) k_softS(const float* __restrict__ adj,
                                               const float* __restrict__ PA) {
    int kn = blockIdx.x;
    int kk = kn / NB, n = kn % NB;
    __shared__ float Ssm[625];
    int tid = threadIdx.x;
    if (tid < 625) {
        float s = 0.f;
        const float* p = g_Spart + (size_t)kn * 16 * 625 + tid;
        #pragma unroll
        for (int ch = 0; ch < 16; ch++) s += p[ch * 625];
        Ssm[tid] = s * (1.f / 4800.f);
    }
    __syncthreads();
    if (tid < 25) {
        int wq = tid;
        float m = -1e30f;
        #pragma unroll
        for (int vi = 0; vi < 25; vi++) m = fmaxf(m, Ssm[vi*25 + wq]);
        float e[25]; float s = 0.f;
        #pragma unroll
        for (int vi = 0; vi < 25; vi++) { e[vi] = expf(Ssm[vi*25 + wq] - m); s += e[vi]; }
        float inv = 1.f / s;
        #pragma unroll
        for (int vi = 0; vi < 25; vi++) {
            int ai = (kk * VV + vi) * VV + wq;
            g_S[kn * 625 + vi * 25 + wq] = e[vi] * inv + adj[ai] + PA[ai];
        }
    }
}

// ---------------- K3: fused GCN v7 (measured 566us) ----------------
#define G7_S   0
#define G7_X   2100
#define G7_ZB  5364
#define G7_TOT 10548
__global__ void __launch_bounds__(256, 4) k_gcn(const float* __restrict__ x,
        const float* __restrict__ bd) {
    extern __shared__ __align__(16) float sm[];
    float* S_s = sm + G7_S;
    float* x_s = sm + G7_X;
    u32*   Zb  = (u32*)(sm + G7_ZB);
    int tid = threadIdx.x;
    int n = blockIdx.y;
    int tile0 = blockIdx.x * 50;

    for (int i = tid; i < 1875; i += 256) {
        int k = i / 625, r = i - k * 625;
        int v = r / 25, w = r - v * 25;
        S_s[k*700 + v*28 + w] = g_S[(k * NB + n) * 625 + r];
    }
    for (int i = tid; i < 225; i += 256) {
        int k = i / 75, rr = i - k * 75;
        int v = rr / 3, pw = rr - v * 3;
        S_s[k*700 + v*28 + 25 + pw] = 0.f;
    }
    for (int i = tid; i < 3200; i += 256) {
        int c = i / 50, j = i - c * 50;
        x_s[c*51 + j] = x[(n * CC + c) * TV + tile0 + j];
    }
    __syncthreads();

    if (tid < 192) {
        int kc = tid, k = kc >> 6, c = kc & 63;
        ull acc[26];
        #pragma unroll
        for (int p = 0; p < 26; p++) acc[p] = 0ull;
        const float* xrow = x_s + c * 51;
        const float* Srow = S_s + k * 700;
        #pragma unroll 5
        for (int v = 0; v < 25; v++) {
            ull xd0 = dup2(xrow[v]);
            ull xd1 = dup2(xrow[25 + v]);
            const ulonglong2* sp2 = (const ulonglong2*)(Srow + v * 28);
            ull sv[13];
            #pragma unroll
            for (int q = 0; q < 6; q++) {
                ulonglong2 u = sp2[q];
                sv[2*q] = u.x; sv[2*q+1] = u.y;
            }
            sv[12] = ((const ull*)(Srow + v * 28))[6];
            #pragma unroll
            for (int p = 0; p < 13; p++) {
                acc[p]      = fma2(sv[p], xd0, acc[p]);
                acc[13 + p] = fma2(sv[p], xd1, acc[13 + p]);
            }
        }
        u32* zr = Zb + kc * 27;
        #pragma unroll
        for (int p = 0; p < 13; p++) {
            float2 f0 = unpk(acc[p]);
            float2 f1 = unpk(acc[13 + p]);
            zr[p]      = bfpack(f0.x, f0.y);
            zr[13 + p] = bfpack(f1.x, f1.y);
        }
    }
    __syncthreads();

    int ty = tid >> 5, tx = tid & 31;
    int ob = ty * 8;
    u32 accb[4][2];
    #pragma unroll
    for (int a = 0; a < 4; a++) { accb[a][0] = 0u; accb[a][1] = 0u; }
    const uint4* __restrict__ wg = (const uint4*)g_wdtb + (ob >> 3);
    #pragma unroll 4
    for (int kc = 0; kc < 192; kc++) {
        uint4 wq = __ldg(wg + kc * 8);
        const u16* zrow = (const u16*)(Zb + kc * 27);
        u32 z0 = splat16(zrow[tx]);
        u32 z1 = splat16(zrow[33 + tx]);
        accb[0][0] = hfma2b(wq.x, z0, accb[0][0]);
        accb[0][1] = hfma2b(wq.x, z1, accb[0][1]);
        accb[1][0] = hfma2b(wq.y, z0, accb[1][0]);
        accb[1][1] = hfma2b(wq.y, z1, accb[1][1]);
        accb[2][0] = hfma2b(wq.z, z0, accb[2][0]);
        accb[2][1] = hfma2b(wq.z, z1, accb[2][1]);
        accb[3][0] = hfma2b(wq.w, z0, accb[3][0]);
        accb[3][1] = hfma2b(wq.w, z1, accb[3][1]);
    }
    int blk = n * 150 + blockIdx.x;
    bool v1 = (tx < 18);
    #pragma unroll
    for (int a = 0; a < 4; a++) {
        int o0 = ob + 2*a;
        float b0 = bd[o0]   + bd[64+o0]   + bd[128+o0];
        float b1 = bd[o0+1] + bd[64+o0+1] + bd[128+o0+1];
        float vx0 = lo2f(accb[a][0]) + b0, vy0 = hi2f(accb[a][0]) + b1;
        float vx1 = lo2f(accb[a][1]) + b0, vy1 = hi2f(accb[a][1]) + b1;
        size_t base0 = (size_t)(n*OCn + o0) * TV + tile0;
        g_y1[base0 + tx] = vx0;
        g_y1[base0 + TV + tx] = vy0;
        if (v1) {
            g_y1[base0 + 32 + tx] = vx1;
            g_y1[base0 + TV + 32 + tx] = vy1;
        }
        float sx = vx0 + (v1 ? vx1 : 0.f);
        float qx = vx0*vx0 + (v1 ? vx1*vx1 : 0.f);
        float sy = vy0 + (v1 ? vy1 : 0.f);
        float qy = vy0*vy0 + (v1 ? vy1*vy1 : 0.f);
        sx = wredsum(sx); qx = wredsum(qx);
        sy = wredsum(sy); qy = wredsum(qy);
        if (tx == 0) {
            g_ps1[o0*9600 + blk] = sx;  g_pq1[o0*9600 + blk] = qx;
            g_ps1[(o0+1)*9600 + blk] = sy;  g_pq1[(o0+1)*9600 + blk] = qy;
        }
    }
}

// ---------------- BN final reductions (deterministic) ----------------
__device__ __forceinline__ void bnsum_body(const float* ps, const float* pq,
                                           int cnt, int off) {
    int o = blockIdx.x;
    __shared__ float sh[512];
    float s = 0.f, q = 0.f;
    for (int i = threadIdx.x; i < cnt; i += 256) {
        s += ps[o*cnt + i];
        q += pq[o*cnt + i];
    }
    sh[threadIdx.x] = s; sh[256 + threadIdx.x] = q;
    __syncthreads();
    for (int st = 128; st; st >>= 1) {
        if (threadIdx.x < st) {
            sh[threadIdx.x] += sh[threadIdx.x + st];
            sh[256 + threadIdx.x] += sh[256 + threadIdx.x + st];
        }
        __syncthreads();
    }
    if (threadIdx.x == 0) {
        g_stats[off + o] = sh[0];
        g_stats[off + 64 + o] = sh[256];
    }
}
__global__ void k_bnsum1() { bnsum_body(g_ps1, g_pq1, 9600, 0); }
__global__ void k_bnsum2() { bnsum_body(g_ps2, g_pq2, 1920, 128); }

// ---------------- K5: z = fp16(relu(bn1(y1)+x)) ----------------
__global__ void __launch_bounds__(256) k_zprep(const float* __restrict__ x,
        const float* __restrict__ g1, const float* __restrict__ b1) {
    int i = blockIdx.x * 256 + threadIdx.x;
    if (i >= YSZ/2) return;
    int c = ((2*i) / TV) & 63;
    const float inv = 1.f / BN_CNT;
    float mu  = g_stats[c] * inv;
    float var = fmaf(-mu, mu, g_stats[64 + c] * inv);
    float sc  = rsqrtf(var + 1e-5f) * g1[c];
    float sh  = fmaf(-mu, sc, b1[c]);
    float2 y  = ((const float2*)g_y1)[i];
    float2 xv = ((const float2*)x)[i];
    float v0 = fmaxf(fmaf(y.x, sc, sh) + xv.x, 0.f);
    float v1 = fmaxf(fmaf(y.y, sc, sh) + xv.y, 0.f);
    __half2 h = __floats2half2_rn(v0, v1);
    ((u32*)g_z)[i] = *(u32*)&h;
}

// ---------------- K6: temporal conv v4 — fp16 z input, reg-prefetch pipeline
__global__ void __launch_bounds__(256, 2) k_tcn(const float* __restrict__ Wt,
                                                const float* __restrict__ bt,
                                                float* __restrict__ out) {
    __shared__ float ys[8 * 456];
    __shared__ __align__(16) float wsm[8 * 9 * 64];
    int n = blockIdx.y;
    int tile0 = blockIdx.x * 256;
    int tid = threadIdx.x;
    int ty = tid >> 5, tx = tid & 31;
    int ob = ty * 8;
    const u32* zb = (const u32*)g_z;

    ull acc2[4][8];
    #pragma unroll
    for (int a = 0; a < 4; a++)
        #pragma unroll
        for (int j = 0; j < 8; j++) acc2[a][j] = 0ull;

    // prologue: prefetch tile for c0 = 0 (1824 u32 pairs = 8 rows x 228)
    u32 pv[8];
    #pragma unroll
    for (int k = 0; k < 8; k++) {
        int li = tid + k * 256;
        u32 val = 0;
        if (li < 1824) {
            int c = li / 228, off2 = li - c * 228;
            int tw = tile0 - 100 + 2 * off2;
            if (tw >= 0 && tw < TV - 1)
                val = zb[(((size_t)(n * CC + c)) * TV + tw) >> 1];
        }
        pv[k] = val;
    }

    for (int c0 = 0; c0 < 64; c0 += 8) {
        __syncthreads();                 // previous compute done reading ys
        #pragma unroll
        for (int k = 0; k < 8; k++) {
            int li = tid + k * 256;
            if (li < 1824) {
                int c = li / 228, off2 = li - c * 228;
                __half2 h = *(__half2*)&pv[k];
                float2 f = __half22float2(h);
                ys[c * 456 + 2 * off2]     = f.x;
                ys[c * 456 + 2 * off2 + 1] = f.y;
            }
        }
        for (int i = tid; i < 8 * 9 * 64; i += 256) {
            int o = i & 63, ck = i >> 6;
            int c = ck / 9, kt = ck - c * 9;
            wsm[i] = Wt[(o * 64 + c0 + c) * 9 + kt];
        }
        __syncthreads();
        // prefetch next tile (overlaps the compute below)
        if (c0 < 56) {
            #pragma unroll
            for (int k = 0; k < 8; k++) {
                int li = tid + k * 256;
                u32 val = 0;
                if (li < 1824) {
                    int c = li / 228, off2 = li - c * 228;
                    int tw = tile0 - 100 + 2 * off2;
                    if (tw >= 0 && tw < TV - 1)
                        val = zb[(((size_t)(n * CC + c0 + 8 + c)) * TV + tw) >> 1];
                }
                pv[k] = val;
            }
        }
        for (int c = 0; c < 8; c++) {
            #pragma unroll 3
            for (int kt = 0; kt < 9; kt++) {
                int ybase = c * 456 + 100 + 25 * (kt - 4) + tx;
                ull yd[8];
                #pragma unroll
                for (int j = 0; j < 8; j++) yd[j] = dup2(ys[ybase + 32 * j]);
                const ulonglong2* wp2 = (const ulonglong2*)(wsm + (c * 9 + kt) * 64 + ob);
                ulonglong2 wA = wp2[0];
                ulonglong2 wB = wp2[1];
                #pragma unroll
                for (int j = 0; j < 8; j++) {
                    acc2[0][j] = fma2(wA.x, yd[j], acc2[0][j]);
                    acc2[1][j] = fma2(wA.y, yd[j], acc2[1][j]);
                    acc2[2][j] = fma2(wB.x, yd[j], acc2[2][j]);
                    acc2[3][j] = fma2(wB.y, yd[j], acc2[3][j]);
                }
            }
        }
    }
    int blk = n * 30 + blockIdx.x;
    #pragma unroll
    for (int a = 0; a < 4; a++) {
        int o0 = ob + 2*a;
        float b0 = bt[o0], b1v = bt[o0+1];
        float sx = 0.f, qx = 0.f, sy = 0.f, qy = 0.f;
        #pragma unroll
        for (int j = 0; j < 8; j++) {
            int tw = tile0 + tx + 32 * j;
            if (tw < TV) {
                float2 f = unpk(acc2[a][j]);
                float vx = f.x + b0, vy = f.y + b1v;
                out[(size_t)(n * OCn + o0  ) * TV + tw] = vx;
                out[(size_t)(n * OCn + o0+1) * TV + tw] = vy;
                sx += vx; qx += vx*vx;
                sy += vy; qy += vy*vy;
            }
        }
        sx = wredsum(sx); qx = wredsum(qx);
        sy = wredsum(sy); qy = wredsum(qy);
        if (tx == 0) {
            g_ps2[o0*1920 + blk] = sx;  g_pq2[o0*1920 + blk] = qx;
            g_ps2[(o0+1)*1920 + blk] = sy;  g_pq2[(o0+1)*1920 + blk] = qy;
        }
    }
}

// ---------------- BN2 apply + residual + relu ----------------
__global__ void k_bn2(float* __restrict__ out, const float* __restrict__ x,
                      const float* __restrict__ g2, const float* __restrict__ b2) {
    int idx = blockIdx.x * 256 + threadIdx.x;
    if (idx >= YSZ) return;
    int c = (idx / TV) & 63;
    const float inv = 1.f / BN_CNT;
    float mu  = g_stats[128 + c] * inv;
    float var = fmaf(-mu, mu, g_stats[192 + c] * inv);
    float sc  = rsqrtf(var + 1e-5f) * g2[c];
    float v   = (out[idx] - mu) * sc + b2[c] + x[idx];
    out[idx] = fmaxf(v, 0.f);
}

// ---------------- adj passthrough ----------------
__global__ void k_copyadj(const float* __restrict__ adj, float* __restrict__ out, int count) {
    int i = blockIdx.x * 256 + threadIdx.x;
    if (i < count) out[YSZ + i] = adj[i];
}

// ---------------- launch ----------------
extern "C" void kernel_launch(void* const* d_in, const int* in_sizes, int n_in,
                              void* d_out, int out_size) {
    const float* x   = (const float*)d_in[0];
    const float* adj = (const float*)d_in[1];
    const float* PA  = (const float*)d_in[2];
    const float* Wa  = (const float*)d_in[3];
    const float* ba  = (const float*)d_in[4];
    const float* Wb  = (const float*)d_in[5];
    const float* bb  = (const float*)d_in[6];
    const float* Wd  = (const float*)d_in[7];
    const float* bd  = (const float*)d_in[8];
    const float* g1  = (const float*)d_in[9];
    const float* b1  = (const float*)d_in[10];
    const float* Wt  = (const float*)d_in[11];
    const float* bt  = (const float*)d_in[12];
    const float* g2  = (const float*)d_in[13];
    const float* b2  = (const float*)d_in[14];
    float* out = (float*)d_out;

    static int smem_set = 0;
    if (!smem_set) {
        cudaFuncSetAttribute(k_gcn, cudaFuncAttributeMaxDynamicSharedMemorySize,
                             G7_TOT * sizeof(float));
        smem_set = 1;
    }

    k_projab<<<dim3(8, 64), 256>>>(x, Wa, ba, Wb, bb, Wd);      // 1 (+Wd prep)
    k_scoreP<<<dim3(16, 192), 640>>>();                          // 2
    k_softS<<<192, 640>>>(adj, PA);                              // 3
    k_gcn<<<dim3(150, 64), 256, G7_TOT * sizeof(float)>>>(x, bd); // 4 -> profiled

    int adjcount = out_size - YSZ;
    if (adjcount > 0) {
        if (adjcount > 3 * VV * VV) adjcount = 3 * VV * VV;
        k_copyadj<<<8, 256>>>(adj, out, adjcount);               // 5
    }
    k_bnsum1<<<64, 256>>>();                                     // 6
    k_zprep<<<(YSZ/2 + 255) / 256, 256>>>(x, g1, b1);            // 7
    k_tcn<<<dim3(30, 64), 256>>>(Wt, bt, out);                   // 8

    k_bnsum2<<<64, 256>>>();
    k_bn2<<<(YSZ + 255) / 256, 256>>>(out, x, g2, b2);
}